// round 10
// baseline (speedup 1.0000x reference)
#include <cuda_runtime.h>
#include <math.h>

#define BB 64
#define TT 500
#define SS 50
#define DD 64
#define NTOK (BB*TT)

typedef unsigned long long u64;

__device__ float g_w[(size_t)NTOK*SS];
__device__ float g_e[(size_t)NTOK*DD];
__device__ float g_a[(size_t)NTOK*DD];
__device__ float g_r[(size_t)NTOK*DD];

__device__ __forceinline__ float fast_sigmoid(float x) {
    return 1.f / (1.f + __expf(-x));
}
__device__ __forceinline__ float fast_tanh(float x) {
    return fmaf(2.f, fast_sigmoid(2.f * x), -1.f);
}

// ---- packed f32x2 helpers ----
__device__ __forceinline__ u64 ffma2(u64 a, u64 b, u64 c) {
    u64 d;
    asm("fma.rn.f32x2 %0, %1, %2, %3;" : "=l"(d) : "l"(a), "l"(b), "l"(c));
    return d;
}
__device__ __forceinline__ u64 fadd2(u64 a, u64 b) {
    u64 d;
    asm("add.rn.f32x2 %0, %1, %2;" : "=l"(d) : "l"(a), "l"(b));
    return d;
}
__device__ __forceinline__ u64 splat2(float x) {
    u64 d;
    asm("mov.b64 %0, {%1, %1};" : "=l"(d) : "r"(__float_as_uint(x)));
    return d;
}
__device__ __forceinline__ u64 pack2(float lo, float hi) {
    u64 d;
    asm("mov.b64 %0, {%1, %2};" : "=l"(d) : "r"(__float_as_uint(lo)), "r"(__float_as_uint(hi)));
    return d;
}
__device__ __forceinline__ float2 unpack2(u64 v) {
    unsigned int lo, hi;
    asm("mov.b64 {%0, %1}, %2;" : "=r"(lo), "=r"(hi) : "l"(v));
    return make_float2(__uint_as_float(lo), __uint_as_float(hi));
}

extern __shared__ float dynsh[];

// ============================================================
// k_front: FUSED scores-softmax + e/a gates. (unchanged, measured 41us)
// ============================================================
#define SROW 52
__global__ __launch_bounds__(256) void k_front(const int* __restrict__ concept,
                                               const int* __restrict__ correct,
                                               const int* __restrict__ nc_ptr,
                                               const float* __restrict__ ek,
                                               const float* __restrict__ ev,
                                               const float* __restrict__ Mk,
                                               const float* __restrict__ We,
                                               const float* __restrict__ be,
                                               const float* __restrict__ Wa,
                                               const float* __restrict__ ba) {
    float* sMkT = dynsh;                  // 3360
    float* sWe  = dynsh + 3360;           // 4096
    float* sWa  = dynsh + 7456;           // 4096
    float* sxk  = dynsh + 11552;          // 4096
    float* sxv  = dynsh + 15648;          // 4096
    __shared__ int sc_[64], sidx[64];

    int tid = threadIdx.x;
    int base = blockIdx.x * 64;
    int td = tid & 15, tt = tid >> 4;
    int nc = *nc_ptr;

    for (int q = tid; q < 3360; q += 256) sMkT[q] = 0.f;
    if (tid < 64) {
        int c = concept[base + tid];
        sc_[tid] = c;
        sidx[tid] = c + nc * correct[base + tid];
    }
    __syncthreads();
    for (int q = tid; q < SS * DD; q += 256) {
        int s = q >> 6, k = q & 63;
        sMkT[k * SROW + s] = Mk[q];
    }
    {
        float4* sWe4w = (float4*)sWe;
        float4* sWa4w = (float4*)sWa;
        const float4* We4 = (const float4*)We;
        const float4* Wa4 = (const float4*)Wa;
        for (int q = tid; q < 1024; q += 256) {
            sWe4w[q] = We4[q];
            sWa4w[q] = Wa4[q];
        }
    }
    __syncthreads();

    {
        float4* sxk4 = (float4*)sxk;
        float4* sxv4 = (float4*)sxv;
        const float4* ek4 = (const float4*)ek;
        const float4* ev4 = (const float4*)ev;
        for (int q = tid; q < 1024; q += 256) {
            int tok = q >> 4, kk = q & 15;
            sxk4[q] = ek4[(size_t)sc_[tok] * 16 + kk];
            sxv4[q] = ev4[(size_t)sidx[tok] * 16 + kk];
        }
    }
    __syncthreads();

    // part 1: scores + softmax
    {
        const float4* sM4 = (const float4*)sMkT;
        const float4* sx4 = (const float4*)sxk;
        u64 acc[4][2];
#pragma unroll
        for (int j = 0; j < 4; ++j) { acc[j][0] = 0ull; acc[j][1] = 0ull; }

#pragma unroll
        for (int kk = 0; kk < 16; ++kk) {
            ulonglong2 w0 = *(const ulonglong2*)(sM4 + (4 * kk + 0) * 13 + td);
            ulonglong2 w1 = *(const ulonglong2*)(sM4 + (4 * kk + 1) * 13 + td);
            ulonglong2 w2 = *(const ulonglong2*)(sM4 + (4 * kk + 2) * 13 + td);
            ulonglong2 w3 = *(const ulonglong2*)(sM4 + (4 * kk + 3) * 13 + td);
#pragma unroll
            for (int j = 0; j < 4; ++j) {
                float4 xv = sx4[(tt + 16 * j) * 16 + kk];
                u64 x0 = splat2(xv.x), x1 = splat2(xv.y), x2 = splat2(xv.z), x3 = splat2(xv.w);
                acc[j][0] = ffma2(x0, w0.x, acc[j][0]);
                acc[j][1] = ffma2(x0, w0.y, acc[j][1]);
                acc[j][0] = ffma2(x1, w1.x, acc[j][0]);
                acc[j][1] = ffma2(x1, w1.y, acc[j][1]);
                acc[j][0] = ffma2(x2, w2.x, acc[j][0]);
                acc[j][1] = ffma2(x2, w2.y, acc[j][1]);
                acc[j][0] = ffma2(x3, w3.x, acc[j][0]);
                acc[j][1] = ffma2(x3, w3.y, acc[j][1]);
            }
        }

#pragma unroll
        for (int j = 0; j < 4; ++j) {
            float2 a01 = unpack2(acc[j][0]);
            float2 a23 = unpack2(acc[j][1]);
            float e0 = (4 * td + 0) < SS ? __expf(a01.x) : 0.f;
            float e1 = (4 * td + 1) < SS ? __expf(a01.y) : 0.f;
            float e2 = (4 * td + 2) < SS ? __expf(a23.x) : 0.f;
            float e3 = (4 * td + 3) < SS ? __expf(a23.y) : 0.f;
            float p = e0 + e1 + e2 + e3;
            p += __shfl_xor_sync(0xffffffffu, p, 1);
            p += __shfl_xor_sync(0xffffffffu, p, 2);
            p += __shfl_xor_sync(0xffffffffu, p, 4);
            p += __shfl_xor_sync(0xffffffffu, p, 8);
            float inv = 1.f / p;
            int tok = base + tt + 16 * j;
            float* gwp = g_w + (size_t)tok * SS + 4 * td;
            if (td < 12) {
                *(float2*)gwp       = make_float2(e0 * inv, e1 * inv);
                *(float2*)(gwp + 2) = make_float2(e2 * inv, e3 * inv);
            } else if (td == 12) {
                *(float2*)gwp       = make_float2(e0 * inv, e1 * inv);
            }
        }
    }

    // part 2: e/a gates
    {
        const float4* sWe4 = (const float4*)sWe;
        const float4* sWa4 = (const float4*)sWa;
        const float4* sx4 = (const float4*)sxv;
        u64 ae[4][2], aa[4][2];
#pragma unroll
        for (int j = 0; j < 4; ++j) {
            ae[j][0] = ae[j][1] = 0ull;
            aa[j][0] = aa[j][1] = 0ull;
        }

#pragma unroll
        for (int kk = 0; kk < 16; ++kk) {
            ulonglong2 e0 = *(const ulonglong2*)(sWe4 + (4 * kk + 0) * 16 + td);
            ulonglong2 e1 = *(const ulonglong2*)(sWe4 + (4 * kk + 1) * 16 + td);
            ulonglong2 e2 = *(const ulonglong2*)(sWe4 + (4 * kk + 2) * 16 + td);
            ulonglong2 e3 = *(const ulonglong2*)(sWe4 + (4 * kk + 3) * 16 + td);
            ulonglong2 a0 = *(const ulonglong2*)(sWa4 + (4 * kk + 0) * 16 + td);
            ulonglong2 a1 = *(const ulonglong2*)(sWa4 + (4 * kk + 1) * 16 + td);
            ulonglong2 a2 = *(const ulonglong2*)(sWa4 + (4 * kk + 2) * 16 + td);
            ulonglong2 a3 = *(const ulonglong2*)(sWa4 + (4 * kk + 3) * 16 + td);
#pragma unroll
            for (int j = 0; j < 4; ++j) {
                float4 xv = sx4[(tt + 16 * j) * 16 + kk];
                u64 x0 = splat2(xv.x), x1 = splat2(xv.y), x2 = splat2(xv.z), x3 = splat2(xv.w);
                ae[j][0] = ffma2(x0, e0.x, ae[j][0]);
                ae[j][1] = ffma2(x0, e0.y, ae[j][1]);
                aa[j][0] = ffma2(x0, a0.x, aa[j][0]);
                aa[j][1] = ffma2(x0, a0.y, aa[j][1]);
                ae[j][0] = ffma2(x1, e1.x, ae[j][0]);
                ae[j][1] = ffma2(x1, e1.y, ae[j][1]);
                aa[j][0] = ffma2(x1, a1.x, aa[j][0]);
                aa[j][1] = ffma2(x1, a1.y, aa[j][1]);
                ae[j][0] = ffma2(x2, e2.x, ae[j][0]);
                ae[j][1] = ffma2(x2, e2.y, ae[j][1]);
                aa[j][0] = ffma2(x2, a2.x, aa[j][0]);
                aa[j][1] = ffma2(x2, a2.y, aa[j][1]);
                ae[j][0] = ffma2(x3, e3.x, ae[j][0]);
                ae[j][1] = ffma2(x3, e3.y, ae[j][1]);
                aa[j][0] = ffma2(x3, a3.x, aa[j][0]);
                aa[j][1] = ffma2(x3, a3.y, aa[j][1]);
            }
        }

        float4 bev = *(const float4*)(be + 4 * td);
        float4 bav = *(const float4*)(ba + 4 * td);
#pragma unroll
        for (int j = 0; j < 4; ++j) {
            size_t tok = (size_t)(base + tt + 16 * j);
            float2 ae01 = unpack2(ae[j][0]);
            float2 ae23 = unpack2(ae[j][1]);
            float2 aa01 = unpack2(aa[j][0]);
            float2 aa23 = unpack2(aa[j][1]);
            float4 eo, ao;
            eo.x = fast_sigmoid(ae01.x + bev.x);
            eo.y = fast_sigmoid(ae01.y + bev.y);
            eo.z = fast_sigmoid(ae23.x + bev.z);
            eo.w = fast_sigmoid(ae23.y + bev.w);
            ao.x = fast_tanh(aa01.x + bav.x);
            ao.y = fast_tanh(aa01.y + bav.y);
            ao.z = fast_tanh(aa23.x + bav.z);
            ao.w = fast_tanh(aa23.y + bav.w);
            *(float4*)(g_e + tok * DD + 4 * td) = eo;
            *(float4*)(g_a + tok * DD + 4 * td) = ao;
        }
    }
}

// ============================================================
// k_scan: 128 blocks = (b, d-half), 256 thr -> ONE wave on 148 SMs.
// dl = tid>>3 (32 dims), h = tid&7 (8 s-states each, padded 50->64).
// Shuffle-free: packed partials -> smem (single buffer) -> per-chunk
// packed-add reduction. CH=20, 2 barriers/chunk.
// smem floats: srp u64[CH*256] @0 (10240 f) | sw 2*CH*64 @10240 |
// se 2*CH*32 @12800 | sa 2*CH*32 @14080. Total 15360 floats (60KB).
// ============================================================
#define CH 20
#define SW_OFF 10240
#define SE_OFF 12800
#define SA_OFF 14080
#define SCAN_SMEM_FLOATS 15360

__global__ __launch_bounds__(256) void k_scan(const float* __restrict__ Mv0) {
    u64*   srp = (u64*)dynsh;                 // [tl][dl][h]  (single buffer)
    float* sw  = dynsh + SW_OFF;              // [buf][tl][64]
    float* se  = dynsh + SE_OFF;              // [buf][tl][32]
    float* sa  = dynsh + SA_OFF;              // [buf][tl][32]

    int b = blockIdx.x >> 1, half = blockIdx.x & 1;
    int tid = threadIdx.x;
    int dl = tid >> 3, h = tid & 7;
    int d = half * 32 + dl;
    int sbase = h * 8;

    // zero w pads (s in [50,64)) for both buffers, all tl
    for (int q = tid; q < 2 * CH * 14; q += 256) {
        int bf = q / (CH * 14), rem = q % (CH * 14), t = rem / 14, p = rem % 14;
        sw[(bf * CH + t) * 64 + 50 + p] = 0.f;
    }

    u64 mv2[4];
#pragma unroll
    for (int i = 0; i < 4; i++) {
        int s0 = sbase + 2 * i, s1 = s0 + 1;
        float lo = (s0 < SS) ? Mv0[s0 * DD + d] : 0.f;
        float hi = (s1 < SS) ? Mv0[s1 * DD + d] : 0.f;
        mv2[i] = pack2(lo, hi);
    }

    const float* gw = g_w + (size_t)b * TT * SS;
    const float* ge = g_e + (size_t)b * TT * DD + half * 32;
    const float* ga = g_a + (size_t)b * TT * DD + half * 32;
    float* gr = g_r + (size_t)b * TT * DD + half * 32;

    // staging roles:
    //   w: CH*25 = 500 float2 loads -> 2 per thread
    //   e: CH*8  = 160 float4 loads -> tid < 160
    //   a: CH*8  = 160 float4 loads -> tid >= 96
    float2 wreg[2];
    float4 eareg, areg;
    bool do_e = tid < 160;
    bool do_a = tid >= 96;
    int et = tid >> 3, ep = tid & 7;
    int at = (tid - 96) >> 3, ap = (tid - 96) & 7;

#pragma unroll
    for (int n = 0; n < 2; n++) {
        int q = tid + 256 * n;
        if (q < CH * 25) { int t = q / 25, p = q % 25; wreg[n] = *(const float2*)(gw + (size_t)t * SS + 2 * p); }
    }
    if (do_e) eareg = *(const float4*)(ge + (size_t)et * DD + 4 * ep);
    if (do_a) areg  = *(const float4*)(ga + (size_t)at * DD + 4 * ap);

#pragma unroll
    for (int n = 0; n < 2; n++) {
        int q = tid + 256 * n;
        if (q < CH * 25) { int t = q / 25, p = q % 25; *(float2*)&sw[t * 64 + 2 * p] = wreg[n]; }
    }
    if (do_e) *(float4*)&se[et * 32 + 4 * ep] = eareg;
    if (do_a) *(float4*)&sa[at * 32 + 4 * ap] = areg;
    __syncthreads();

    for (int c = 0; c < TT / CH; ++c) {
        int cur = c & 1;
        int curCH = cur * CH;
        if (c < TT / CH - 1) {
            int t0 = (c + 1) * CH;
#pragma unroll
            for (int n = 0; n < 2; n++) {
                int q = tid + 256 * n;
                if (q < CH * 25) { int t = q / 25, p = q % 25; wreg[n] = *(const float2*)(gw + (size_t)(t0 + t) * SS + 2 * p); }
            }
            if (do_e) eareg = *(const float4*)(ge + (size_t)(t0 + et) * DD + 4 * ep);
            if (do_a) areg  = *(const float4*)(ga + (size_t)(t0 + at) * DD + 4 * ap);
        }

#pragma unroll
        for (int tl = 0; tl < CH; ++tl) {
            float e_d = se[(curCH + tl) * 32 + dl];
            float a_d = sa[(curCH + tl) * 32 + dl];
            u64 ne2 = splat2(-e_d);
            u64 a2 = splat2(a_d);
            ulonglong2 wA = *(const ulonglong2*)&sw[(curCH + tl) * 64 + sbase];
            ulonglong2 wB = *(const ulonglong2*)&sw[(curCH + tl) * 64 + sbase + 4];
            u64 r2a = ffma2(wA.x, mv2[0], 0ull);
            u64 r2b = ffma2(wA.y, mv2[1], 0ull);
            r2a = ffma2(wB.x, mv2[2], r2a);
            r2b = ffma2(wB.y, mv2[3], r2b);
            srp[(size_t)tl * 256 + tid] = fadd2(r2a, r2b);
            mv2[0] = ffma2(wA.x, ffma2(mv2[0], ne2, a2), mv2[0]);
            mv2[1] = ffma2(wA.y, ffma2(mv2[1], ne2, a2), mv2[1]);
            mv2[2] = ffma2(wB.x, ffma2(mv2[2], ne2, a2), mv2[2]);
            mv2[3] = ffma2(wB.y, ffma2(mv2[3], ne2, a2), mv2[3]);
        }
        __syncthreads();

        // reduction: CH*32 = 640 outputs over 256 threads
        {
            int t0 = c * CH;
#pragma unroll
            for (int o = tid; o < CH * 32; o += 256) {
                int tl = o >> 5, odl = o & 31;
                const u64* pp = srp + (size_t)tl * 256 + odl * 8;
                u64 s0 = fadd2(pp[0], pp[1]);
                u64 s1 = fadd2(pp[2], pp[3]);
                u64 s2 = fadd2(pp[4], pp[5]);
                u64 s3 = fadd2(pp[6], pp[7]);
                u64 s = fadd2(fadd2(s0, s1), fadd2(s2, s3));
                float2 rr = unpack2(s);
                gr[(size_t)(t0 + tl) * DD + odl] = rr.x + rr.y;
            }
        }
        if (c < TT / CH - 1) {
            int nb = (cur ^ 1) * CH;
#pragma unroll
            for (int n = 0; n < 2; n++) {
                int q = tid + 256 * n;
                if (q < CH * 25) { int t = q / 25, p = q % 25; *(float2*)&sw[(nb + t) * 64 + 2 * p] = wreg[n]; }
            }
            if (do_e) *(float4*)&se[(nb + et) * 32 + 4 * ep] = eareg;
            if (do_a) *(float4*)&sa[(nb + at) * 32 + 4 * ap] = areg;
        }
        __syncthreads();
    }
}

// ============================================================
// k_out: unchanged (measured ~32us).
// ============================================================
__global__ __launch_bounds__(256) void k_out(const int* __restrict__ concept,
                                             const float* __restrict__ ek,
                                             const float* __restrict__ Wf,
                                             const float* __restrict__ bf,
                                             const float* __restrict__ Wab,
                                             const float* __restrict__ bab,
                                             const float* __restrict__ Wd,
                                             const float* __restrict__ bd,
                                             float* __restrict__ out) {
    float* sWf = dynsh;
    float* sx  = dynsh + 8192;
    __shared__ int sc_[64];

    int tid = threadIdx.x;
    int base = blockIdx.x * 64;
    int td = tid & 15, tt = tid >> 4;

    float4* sWf4w = (float4*)sWf;
    const float4* Wf4 = (const float4*)Wf;
    for (int q = tid; q < 2048; q += 256) sWf4w[q] = Wf4[q];
    if (tid < 64) sc_[tid] = concept[base + tid];
    __syncthreads();

    float4* sx4 = (float4*)sx;
    const float4* gr4 = (const float4*)g_r;
    const float4* ek4 = (const float4*)ek;
    for (int q = tid; q < 1024; q += 256) {
        int tok = q >> 4, kk = q & 15;
        sx4[tok * 32 + kk] = gr4[(size_t)(base + tok) * 16 + kk];
        sx4[tok * 32 + 16 + kk] = ek4[(size_t)sc_[tok] * 16 + kk];
    }
    __syncthreads();

    const float4* sWf4 = (const float4*)sWf;
    u64 acc[4][2];
#pragma unroll
    for (int j = 0; j < 4; ++j) { acc[j][0] = 0ull; acc[j][1] = 0ull; }

#pragma unroll
    for (int kk = 0; kk < 32; ++kk) {
        ulonglong2 w0 = *(const ulonglong2*)(sWf4 + (4 * kk + 0) * 16 + td);
        ulonglong2 w1 = *(const ulonglong2*)(sWf4 + (4 * kk + 1) * 16 + td);
        ulonglong2 w2 = *(const ulonglong2*)(sWf4 + (4 * kk + 2) * 16 + td);
        ulonglong2 w3 = *(const ulonglong2*)(sWf4 + (4 * kk + 3) * 16 + td);
#pragma unroll
        for (int j = 0; j < 4; ++j) {
            float4 xv = sx4[(tt + 16 * j) * 32 + kk];
            u64 x0 = splat2(xv.x), x1 = splat2(xv.y), x2 = splat2(xv.z), x3 = splat2(xv.w);
            acc[j][0] = ffma2(x0, w0.x, acc[j][0]);
            acc[j][1] = ffma2(x0, w0.y, acc[j][1]);
            acc[j][0] = ffma2(x1, w1.x, acc[j][0]);
            acc[j][1] = ffma2(x1, w1.y, acc[j][1]);
            acc[j][0] = ffma2(x2, w2.x, acc[j][0]);
            acc[j][1] = ffma2(x2, w2.y, acc[j][1]);
            acc[j][0] = ffma2(x3, w3.x, acc[j][0]);
            acc[j][1] = ffma2(x3, w3.y, acc[j][1]);
        }
    }

    float4 bfv = *(const float4*)(bf + 4 * td);
    float4 wabv = *(const float4*)(Wab + 4 * td);
    float4 wdv = *(const float4*)(Wd + 4 * td);
    float bab0 = bab[0], bd0 = bd[0];

#pragma unroll
    for (int j = 0; j < 4; ++j) {
        int tok = tt + 16 * j;
        float2 a01 = unpack2(acc[j][0]);
        float2 a23 = unpack2(acc[j][1]);
        float f0 = fast_tanh(a01.x + bfv.x);
        float f1 = fast_tanh(a01.y + bfv.y);
        float f2 = fast_tanh(a23.x + bfv.z);
        float f3 = fast_tanh(a23.y + bfv.w);
        float pa = f0 * wabv.x + f1 * wabv.y + f2 * wabv.z + f3 * wabv.w;
        float4 kd = *(const float4*)&sx[tok * 128 + 64 + 4 * td];
        float pq = kd.x * wdv.x + kd.y * wdv.y + kd.z * wdv.z + kd.w * wdv.w;
#pragma unroll
        for (int o = 8; o > 0; o >>= 1) {
            pa += __shfl_xor_sync(0xffffffffu, pa, o);
            pq += __shfl_xor_sync(0xffffffffu, pq, o);
        }
        if (td == 0) {
            float val = 3.f * fast_tanh(pa + bab0) - fast_tanh(pq + bd0);
            out[base + tok] = fast_sigmoid(val);
        }
    }
}

// ============================================================
extern "C" void kernel_launch(void* const* d_in, const int* in_sizes, int n_in,
                              void* d_out, int out_size) {
    const int*   concept = (const int*)d_in[0];
    const int*   correct = (const int*)d_in[1];
    const int*   nc      = (const int*)d_in[2];
    const float* ek      = (const float*)d_in[3];
    const float* ev      = (const float*)d_in[4];
    const float* Mk      = (const float*)d_in[5];
    const float* Mv0     = (const float*)d_in[6];
    const float* Wf      = (const float*)d_in[7];
    const float* bf      = (const float*)d_in[8];
    const float* We      = (const float*)d_in[9];
    const float* be      = (const float*)d_in[10];
    const float* Wa      = (const float*)d_in[11];
    const float* ba      = (const float*)d_in[12];
    const float* Wab     = (const float*)d_in[13];
    const float* bab     = (const float*)d_in[14];
    const float* Wd      = (const float*)d_in[15];
    const float* bd      = (const float*)d_in[16];
    float* out = (float*)d_out;

    const int FRONT_SMEM = 19744 * sizeof(float);            // ~77KB
    const int SCAN_SMEM  = SCAN_SMEM_FLOATS * sizeof(float); // 60KB
    const int OUT_SMEM   = 16384 * sizeof(float);            // 64KB
    cudaFuncSetAttribute(k_front, cudaFuncAttributeMaxDynamicSharedMemorySize, FRONT_SMEM);
    cudaFuncSetAttribute(k_scan,  cudaFuncAttributeMaxDynamicSharedMemorySize, SCAN_SMEM);
    cudaFuncSetAttribute(k_out,   cudaFuncAttributeMaxDynamicSharedMemorySize, OUT_SMEM);

    k_front<<<500, 256, FRONT_SMEM>>>(concept, correct, nc, ek, ev, Mk, We, be, Wa, ba);
    k_scan<<<128, 256, SCAN_SMEM>>>(Mv0);
    k_out<<<500, 256, OUT_SMEM>>>(concept, ek, Wf, bf, Wab, bab, Wd, bd, out);
}

// round 11
// speedup vs baseline: 1.0275x; 1.0275x over previous
#include <cuda_runtime.h>
#include <math.h>

#define BB 64
#define TT 500
#define SS 50
#define DD 64
#define NTOK (BB*TT)

typedef unsigned long long u64;

__device__ float g_w[(size_t)NTOK*SS];
__device__ float g_e[(size_t)NTOK*DD];
__device__ float g_a[(size_t)NTOK*DD];
__device__ float g_r[(size_t)NTOK*DD];

__device__ __forceinline__ float fast_sigmoid(float x) {
    return 1.f / (1.f + __expf(-x));
}
__device__ __forceinline__ float fast_tanh(float x) {
    return fmaf(2.f, fast_sigmoid(2.f * x), -1.f);
}

// ---- packed f32x2 helpers ----
__device__ __forceinline__ u64 ffma2(u64 a, u64 b, u64 c) {
    u64 d;
    asm("fma.rn.f32x2 %0, %1, %2, %3;" : "=l"(d) : "l"(a), "l"(b), "l"(c));
    return d;
}
__device__ __forceinline__ u64 fadd2(u64 a, u64 b) {
    u64 d;
    asm("add.rn.f32x2 %0, %1, %2;" : "=l"(d) : "l"(a), "l"(b));
    return d;
}
__device__ __forceinline__ u64 splat2(float x) {
    u64 d;
    asm("mov.b64 %0, {%1, %1};" : "=l"(d) : "r"(__float_as_uint(x)));
    return d;
}
__device__ __forceinline__ u64 pack2(float lo, float hi) {
    u64 d;
    asm("mov.b64 %0, {%1, %2};" : "=l"(d) : "r"(__float_as_uint(lo)), "r"(__float_as_uint(hi)));
    return d;
}
__device__ __forceinline__ float2 unpack2(u64 v) {
    unsigned int lo, hi;
    asm("mov.b64 {%0, %1}, %2;" : "=r"(lo), "=r"(hi) : "l"(v));
    return make_float2(__uint_as_float(lo), __uint_as_float(hi));
}

extern __shared__ float dynsh[];

// ============================================================
// k_front: FUSED scores-softmax + e/a gates. Grid 250, 2 tiles of 64
// tokens per block: weights staged ONCE, single wave (2 blocks/SM).
// ============================================================
#define SROW 52
__global__ __launch_bounds__(256) void k_front(const int* __restrict__ concept,
                                               const int* __restrict__ correct,
                                               const int* __restrict__ nc_ptr,
                                               const float* __restrict__ ek,
                                               const float* __restrict__ ev,
                                               const float* __restrict__ Mk,
                                               const float* __restrict__ We,
                                               const float* __restrict__ be,
                                               const float* __restrict__ Wa,
                                               const float* __restrict__ ba) {
    float* sMkT = dynsh;                  // 3360 (+16 pad inside)
    float* sWe  = dynsh + 3376;           // 4096
    float* sWa  = dynsh + 7472;           // 4096
    float* sxk  = dynsh + 11568;          // 4096
    float* sxv  = dynsh + 15664;          // 4096   total 19760 floats
    __shared__ int sc_[64], sidx[64];

    int tid = threadIdx.x;
    int td = tid & 15, tt = tid >> 4;
    int nc = *nc_ptr;

    // ---- stage weights once ----
    for (int q = tid; q < 3376; q += 256) sMkT[q] = 0.f;
    __syncthreads();
    for (int q = tid; q < SS * DD; q += 256) {
        int s = q >> 6, k = q & 63;
        sMkT[k * SROW + s] = Mk[q];
    }
    {
        float4* sWe4w = (float4*)sWe;
        float4* sWa4w = (float4*)sWa;
        const float4* We4 = (const float4*)We;
        const float4* Wa4 = (const float4*)Wa;
        for (int q = tid; q < 1024; q += 256) {
            sWe4w[q] = We4[q];
            sWa4w[q] = Wa4[q];
        }
    }
    float4 bev = *(const float4*)(be + 4 * td);
    float4 bav = *(const float4*)(ba + 4 * td);

    for (int tile = 0; tile < 2; ++tile) {
        int base = (blockIdx.x * 2 + tile) * 64;

        __syncthreads();   // weights ready (tile0) / prev compute done (tile1)
        if (tid < 64) {
            int c = concept[base + tid];
            sc_[tid] = c;
            sidx[tid] = c + nc * correct[base + tid];
        }
        __syncthreads();
        {
            float4* sxk4 = (float4*)sxk;
            float4* sxv4 = (float4*)sxv;
            const float4* ek4 = (const float4*)ek;
            const float4* ev4 = (const float4*)ev;
            for (int q = tid; q < 1024; q += 256) {
                int tok = q >> 4, kk = q & 15;
                sxk4[q] = ek4[(size_t)sc_[tok] * 16 + kk];
                sxv4[q] = ev4[(size_t)sidx[tok] * 16 + kk];
            }
        }
        __syncthreads();

        // part 1: scores + softmax
        {
            const float4* sM4 = (const float4*)sMkT;
            const float4* sx4 = (const float4*)sxk;
            u64 acc[4][2];
#pragma unroll
            for (int j = 0; j < 4; ++j) { acc[j][0] = 0ull; acc[j][1] = 0ull; }

#pragma unroll
            for (int kk = 0; kk < 16; ++kk) {
                ulonglong2 w0 = *(const ulonglong2*)(sM4 + (4 * kk + 0) * 13 + td);
                ulonglong2 w1 = *(const ulonglong2*)(sM4 + (4 * kk + 1) * 13 + td);
                ulonglong2 w2 = *(const ulonglong2*)(sM4 + (4 * kk + 2) * 13 + td);
                ulonglong2 w3 = *(const ulonglong2*)(sM4 + (4 * kk + 3) * 13 + td);
#pragma unroll
                for (int j = 0; j < 4; ++j) {
                    float4 xv = sx4[(tt + 16 * j) * 16 + kk];
                    u64 x0 = splat2(xv.x), x1 = splat2(xv.y), x2 = splat2(xv.z), x3 = splat2(xv.w);
                    acc[j][0] = ffma2(x0, w0.x, acc[j][0]);
                    acc[j][1] = ffma2(x0, w0.y, acc[j][1]);
                    acc[j][0] = ffma2(x1, w1.x, acc[j][0]);
                    acc[j][1] = ffma2(x1, w1.y, acc[j][1]);
                    acc[j][0] = ffma2(x2, w2.x, acc[j][0]);
                    acc[j][1] = ffma2(x2, w2.y, acc[j][1]);
                    acc[j][0] = ffma2(x3, w3.x, acc[j][0]);
                    acc[j][1] = ffma2(x3, w3.y, acc[j][1]);
                }
            }

#pragma unroll
            for (int j = 0; j < 4; ++j) {
                float2 a01 = unpack2(acc[j][0]);
                float2 a23 = unpack2(acc[j][1]);
                float e0 = (4 * td + 0) < SS ? __expf(a01.x) : 0.f;
                float e1 = (4 * td + 1) < SS ? __expf(a01.y) : 0.f;
                float e2 = (4 * td + 2) < SS ? __expf(a23.x) : 0.f;
                float e3 = (4 * td + 3) < SS ? __expf(a23.y) : 0.f;
                float p = e0 + e1 + e2 + e3;
                p += __shfl_xor_sync(0xffffffffu, p, 1);
                p += __shfl_xor_sync(0xffffffffu, p, 2);
                p += __shfl_xor_sync(0xffffffffu, p, 4);
                p += __shfl_xor_sync(0xffffffffu, p, 8);
                float inv = 1.f / p;
                int tok = base + tt + 16 * j;
                float* gwp = g_w + (size_t)tok * SS + 4 * td;
                if (td < 12) {
                    *(float2*)gwp       = make_float2(e0 * inv, e1 * inv);
                    *(float2*)(gwp + 2) = make_float2(e2 * inv, e3 * inv);
                } else if (td == 12) {
                    *(float2*)gwp       = make_float2(e0 * inv, e1 * inv);
                }
            }
        }

        // part 2: e/a gates
        {
            const float4* sWe4 = (const float4*)sWe;
            const float4* sWa4 = (const float4*)sWa;
            const float4* sx4 = (const float4*)sxv;
            u64 ae[4][2], aa[4][2];
#pragma unroll
            for (int j = 0; j < 4; ++j) {
                ae[j][0] = ae[j][1] = 0ull;
                aa[j][0] = aa[j][1] = 0ull;
            }

#pragma unroll
            for (int kk = 0; kk < 16; ++kk) {
                ulonglong2 e0 = *(const ulonglong2*)(sWe4 + (4 * kk + 0) * 16 + td);
                ulonglong2 e1 = *(const ulonglong2*)(sWe4 + (4 * kk + 1) * 16 + td);
                ulonglong2 e2 = *(const ulonglong2*)(sWe4 + (4 * kk + 2) * 16 + td);
                ulonglong2 e3 = *(const ulonglong2*)(sWe4 + (4 * kk + 3) * 16 + td);
                ulonglong2 a0 = *(const ulonglong2*)(sWa4 + (4 * kk + 0) * 16 + td);
                ulonglong2 a1 = *(const ulonglong2*)(sWa4 + (4 * kk + 1) * 16 + td);
                ulonglong2 a2 = *(const ulonglong2*)(sWa4 + (4 * kk + 2) * 16 + td);
                ulonglong2 a3 = *(const ulonglong2*)(sWa4 + (4 * kk + 3) * 16 + td);
#pragma unroll
                for (int j = 0; j < 4; ++j) {
                    float4 xv = sx4[(tt + 16 * j) * 16 + kk];
                    u64 x0 = splat2(xv.x), x1 = splat2(xv.y), x2 = splat2(xv.z), x3 = splat2(xv.w);
                    ae[j][0] = ffma2(x0, e0.x, ae[j][0]);
                    ae[j][1] = ffma2(x0, e0.y, ae[j][1]);
                    aa[j][0] = ffma2(x0, a0.x, aa[j][0]);
                    aa[j][1] = ffma2(x0, a0.y, aa[j][1]);
                    ae[j][0] = ffma2(x1, e1.x, ae[j][0]);
                    ae[j][1] = ffma2(x1, e1.y, ae[j][1]);
                    aa[j][0] = ffma2(x1, a1.x, aa[j][0]);
                    aa[j][1] = ffma2(x1, a1.y, aa[j][1]);
                    ae[j][0] = ffma2(x2, e2.x, ae[j][0]);
                    ae[j][1] = ffma2(x2, e2.y, ae[j][1]);
                    aa[j][0] = ffma2(x2, a2.x, aa[j][0]);
                    aa[j][1] = ffma2(x2, a2.y, aa[j][1]);
                    ae[j][0] = ffma2(x3, e3.x, ae[j][0]);
                    ae[j][1] = ffma2(x3, e3.y, ae[j][1]);
                    aa[j][0] = ffma2(x3, a3.x, aa[j][0]);
                    aa[j][1] = ffma2(x3, a3.y, aa[j][1]);
                }
            }

#pragma unroll
            for (int j = 0; j < 4; ++j) {
                size_t tok = (size_t)(base + tt + 16 * j);
                float2 ae01 = unpack2(ae[j][0]);
                float2 ae23 = unpack2(ae[j][1]);
                float2 aa01 = unpack2(aa[j][0]);
                float2 aa23 = unpack2(aa[j][1]);
                float4 eo, ao;
                eo.x = fast_sigmoid(ae01.x + bev.x);
                eo.y = fast_sigmoid(ae01.y + bev.y);
                eo.z = fast_sigmoid(ae23.x + bev.z);
                eo.w = fast_sigmoid(ae23.y + bev.w);
                ao.x = fast_tanh(aa01.x + bav.x);
                ao.y = fast_tanh(aa01.y + bav.y);
                ao.z = fast_tanh(aa23.x + bav.z);
                ao.w = fast_tanh(aa23.y + bav.w);
                *(float4*)(g_e + tok * DD + 4 * td) = eo;
                *(float4*)(g_a + tok * DD + 4 * td) = ao;
            }
        }
    }
}

// ============================================================
// k_scan: R9 measured-best: 256 blocks = (b, dq), 128 thr,
// shuffle-free packed partials, CH=20.
// ============================================================
#define CH 20
#define SW_OFF 10240
#define SE_OFF 12800
#define SA_OFF 13440
#define SCAN_SMEM_FLOATS 14080

__global__ __launch_bounds__(128) void k_scan(const float* __restrict__ Mv0) {
    u64*   srp = (u64*)dynsh;                 // [buf][tl][dl][h]
    float* sw  = dynsh + SW_OFF;
    float* se  = dynsh + SE_OFF;
    float* sa  = dynsh + SA_OFF;

    int b = blockIdx.x >> 2, dq = blockIdx.x & 3;
    int tid = threadIdx.x;
    int dl = tid >> 3, h = tid & 7;
    int d = dq * 16 + dl;
    int sbase = h * 8;

    for (int q = tid; q < 2 * CH * 14; q += 128) {
        int bf = q / (CH * 14), rem = q % (CH * 14), t = rem / 14, p = rem % 14;
        sw[(bf * CH + t) * 64 + 50 + p] = 0.f;
    }

    u64 mv2[4];
#pragma unroll
    for (int i = 0; i < 4; i++) {
        int s0 = sbase + 2 * i, s1 = s0 + 1;
        float lo = (s0 < SS) ? Mv0[s0 * DD + d] : 0.f;
        float hi = (s1 < SS) ? Mv0[s1 * DD + d] : 0.f;
        mv2[i] = pack2(lo, hi);
    }

    const float* gw = g_w + (size_t)b * TT * SS;
    const float* ge = g_e + (size_t)b * TT * DD + dq * 16;
    const float* ga = g_a + (size_t)b * TT * DD + dq * 16;
    float* gr = g_r + (size_t)b * TT * DD + dq * 16;

    float2 wreg[4];
    float4 eareg, areg;
    bool do_e = tid < 80;
    bool do_a2 = tid >= 48;
    int et = tid >> 2, ep = tid & 3;
    int at = (tid - 48) >> 2, ap = (tid - 48) & 3;

#pragma unroll
    for (int n = 0; n < 4; n++) {
        int q = tid + 128 * n;
        if (q < CH * 25) { int t = q / 25, p = q % 25; wreg[n] = *(const float2*)(gw + (size_t)t * SS + 2 * p); }
    }
    if (do_e)  eareg = *(const float4*)(ge + (size_t)et * DD + 4 * ep);
    if (do_a2) areg  = *(const float4*)(ga + (size_t)at * DD + 4 * ap);

#pragma unroll
    for (int n = 0; n < 4; n++) {
        int q = tid + 128 * n;
        if (q < CH * 25) { int t = q / 25, p = q % 25; *(float2*)&sw[t * 64 + 2 * p] = wreg[n]; }
    }
    if (do_e)  *(float4*)&se[et * 16 + 4 * ep] = eareg;
    if (do_a2) *(float4*)&sa[at * 16 + 4 * ap] = areg;
    __syncthreads();

    for (int c = 0; c < TT / CH; ++c) {
        int cur = c & 1;
        int curCH = cur * CH;
        if (c < TT / CH - 1) {
            int t0 = (c + 1) * CH;
#pragma unroll
            for (int n = 0; n < 4; n++) {
                int q = tid + 128 * n;
                if (q < CH * 25) { int t = q / 25, p = q % 25; wreg[n] = *(const float2*)(gw + (size_t)(t0 + t) * SS + 2 * p); }
            }
            if (do_e)  eareg = *(const float4*)(ge + (size_t)(t0 + et) * DD + 4 * ep);
            if (do_a2) areg  = *(const float4*)(ga + (size_t)(t0 + at) * DD + 4 * ap);
        }

#pragma unroll
        for (int tl = 0; tl < CH; ++tl) {
            float e_d = se[(curCH + tl) * 16 + dl];
            float a_d = sa[(curCH + tl) * 16 + dl];
            u64 ne2 = splat2(-e_d);
            u64 a2 = splat2(a_d);
            ulonglong2 wA = *(const ulonglong2*)&sw[(curCH + tl) * 64 + sbase];
            ulonglong2 wB = *(const ulonglong2*)&sw[(curCH + tl) * 64 + sbase + 4];
            u64 r2a = ffma2(wA.x, mv2[0], 0ull);
            u64 r2b = ffma2(wA.y, mv2[1], 0ull);
            r2a = ffma2(wB.x, mv2[2], r2a);
            r2b = ffma2(wB.y, mv2[3], r2b);
            srp[(size_t)(curCH + tl) * 128 + tid] = fadd2(r2a, r2b);
            mv2[0] = ffma2(wA.x, ffma2(mv2[0], ne2, a2), mv2[0]);
            mv2[1] = ffma2(wA.y, ffma2(mv2[1], ne2, a2), mv2[1]);
            mv2[2] = ffma2(wB.x, ffma2(mv2[2], ne2, a2), mv2[2]);
            mv2[3] = ffma2(wB.y, ffma2(mv2[3], ne2, a2), mv2[3]);
        }
        __syncthreads();

        {
            int t0 = c * CH;
#pragma unroll
            for (int o = tid; o < CH * 16; o += 128) {
                int tl = o >> 4, odl = o & 15;
                const u64* pp = srp + (size_t)(curCH + tl) * 128 + odl * 8;
                u64 s0 = fadd2(pp[0], pp[1]);
                u64 s1 = fadd2(pp[2], pp[3]);
                u64 s2 = fadd2(pp[4], pp[5]);
                u64 s3 = fadd2(pp[6], pp[7]);
                u64 s = fadd2(fadd2(s0, s1), fadd2(s2, s3));
                float2 rr = unpack2(s);
                gr[(size_t)(t0 + tl) * DD + odl] = rr.x + rr.y;
            }
        }
        if (c < TT / CH - 1) {
            int nb = (cur ^ 1) * CH;
#pragma unroll
            for (int n = 0; n < 4; n++) {
                int q = tid + 128 * n;
                if (q < CH * 25) { int t = q / 25, p = q % 25; *(float2*)&sw[(nb + t) * 64 + 2 * p] = wreg[n]; }
            }
            if (do_e)  *(float4*)&se[(nb + et) * 16 + 4 * ep] = eareg;
            if (do_a2) *(float4*)&sa[(nb + at) * 16 + 4 * ap] = areg;
        }
        __syncthreads();
    }
}

// ============================================================
// k_out: grid 250, 2 tiles of 64 tokens per block. Wf staged once.
// ============================================================
__global__ __launch_bounds__(256) void k_out(const int* __restrict__ concept,
                                             const float* __restrict__ ek,
                                             const float* __restrict__ Wf,
                                             const float* __restrict__ bf,
                                             const float* __restrict__ Wab,
                                             const float* __restrict__ bab,
                                             const float* __restrict__ Wd,
                                             const float* __restrict__ bd,
                                             float* __restrict__ out) {
    float* sWf = dynsh;                 // 8192 floats
    float* sx  = dynsh + 8192;          // 8192 floats
    __shared__ int sc_[64];

    int tid = threadIdx.x;
    int td = tid & 15, tt = tid >> 4;

    float4* sWf4w = (float4*)sWf;
    const float4* Wf4 = (const float4*)Wf;
    for (int q = tid; q < 2048; q += 256) sWf4w[q] = Wf4[q];

    float4 bfv = *(const float4*)(bf + 4 * td);
    float4 wabv = *(const float4*)(Wab + 4 * td);
    float4 wdv = *(const float4*)(Wd + 4 * td);
    float bab0 = bab[0], bd0 = bd[0];

    for (int tile = 0; tile < 2; ++tile) {
        int base = (blockIdx.x * 2 + tile) * 64;

        __syncthreads();   // Wf ready / prev compute done
        if (tid < 64) sc_[tid] = concept[base + tid];
        __syncthreads();

        float4* sx4 = (float4*)sx;
        const float4* gr4 = (const float4*)g_r;
        const float4* ek4 = (const float4*)ek;
        for (int q = tid; q < 1024; q += 256) {
            int tok = q >> 4, kk = q & 15;
            sx4[tok * 32 + kk] = gr4[(size_t)(base + tok) * 16 + kk];
            sx4[tok * 32 + 16 + kk] = ek4[(size_t)sc_[tok] * 16 + kk];
        }
        __syncthreads();

        const float4* sWf4 = (const float4*)sWf;
        u64 acc[4][2];
#pragma unroll
        for (int j = 0; j < 4; ++j) { acc[j][0] = 0ull; acc[j][1] = 0ull; }

#pragma unroll
        for (int kk = 0; kk < 32; ++kk) {
            ulonglong2 w0 = *(const ulonglong2*)(sWf4 + (4 * kk + 0) * 16 + td);
            ulonglong2 w1 = *(const ulonglong2*)(sWf4 + (4 * kk + 1) * 16 + td);
            ulonglong2 w2 = *(const ulonglong2*)(sWf4 + (4 * kk + 2) * 16 + td);
            ulonglong2 w3 = *(const ulonglong2*)(sWf4 + (4 * kk + 3) * 16 + td);
#pragma unroll
            for (int j = 0; j < 4; ++j) {
                float4 xv = sx4[(tt + 16 * j) * 32 + kk];
                u64 x0 = splat2(xv.x), x1 = splat2(xv.y), x2 = splat2(xv.z), x3 = splat2(xv.w);
                acc[j][0] = ffma2(x0, w0.x, acc[j][0]);
                acc[j][1] = ffma2(x0, w0.y, acc[j][1]);
                acc[j][0] = ffma2(x1, w1.x, acc[j][0]);
                acc[j][1] = ffma2(x1, w1.y, acc[j][1]);
                acc[j][0] = ffma2(x2, w2.x, acc[j][0]);
                acc[j][1] = ffma2(x2, w2.y, acc[j][1]);
                acc[j][0] = ffma2(x3, w3.x, acc[j][0]);
                acc[j][1] = ffma2(x3, w3.y, acc[j][1]);
            }
        }

#pragma unroll
        for (int j = 0; j < 4; ++j) {
            int tok = tt + 16 * j;
            float2 a01 = unpack2(acc[j][0]);
            float2 a23 = unpack2(acc[j][1]);
            float f0 = fast_tanh(a01.x + bfv.x);
            float f1 = fast_tanh(a01.y + bfv.y);
            float f2 = fast_tanh(a23.x + bfv.z);
            float f3 = fast_tanh(a23.y + bfv.w);
            float pa = f0 * wabv.x + f1 * wabv.y + f2 * wabv.z + f3 * wabv.w;
            float4 kd = *(const float4*)&sx[tok * 128 + 64 + 4 * td];
            float pq = kd.x * wdv.x + kd.y * wdv.y + kd.z * wdv.z + kd.w * wdv.w;
#pragma unroll
            for (int o = 8; o > 0; o >>= 1) {
                pa += __shfl_xor_sync(0xffffffffu, pa, o);
                pq += __shfl_xor_sync(0xffffffffu, pq, o);
            }
            if (td == 0) {
                float val = 3.f * fast_tanh(pa + bab0) - fast_tanh(pq + bd0);
                out[base + tok] = fast_sigmoid(val);
            }
        }
    }
}

// ============================================================
extern "C" void kernel_launch(void* const* d_in, const int* in_sizes, int n_in,
                              void* d_out, int out_size) {
    const int*   concept = (const int*)d_in[0];
    const int*   correct = (const int*)d_in[1];
    const int*   nc      = (const int*)d_in[2];
    const float* ek      = (const float*)d_in[3];
    const float* ev      = (const float*)d_in[4];
    const float* Mk      = (const float*)d_in[5];
    const float* Mv0     = (const float*)d_in[6];
    const float* Wf      = (const float*)d_in[7];
    const float* bf      = (const float*)d_in[8];
    const float* We      = (const float*)d_in[9];
    const float* be      = (const float*)d_in[10];
    const float* Wa      = (const float*)d_in[11];
    const float* ba      = (const float*)d_in[12];
    const float* Wab     = (const float*)d_in[13];
    const float* bab     = (const float*)d_in[14];
    const float* Wd      = (const float*)d_in[15];
    const float* bd      = (const float*)d_in[16];
    float* out = (float*)d_out;

    const int FRONT_SMEM = 19760 * sizeof(float);            // ~77KB
    const int SCAN_SMEM  = SCAN_SMEM_FLOATS * sizeof(float); // 55KB
    const int OUT_SMEM   = 16384 * sizeof(float);            // 64KB
    cudaFuncSetAttribute(k_front, cudaFuncAttributeMaxDynamicSharedMemorySize, FRONT_SMEM);
    cudaFuncSetAttribute(k_scan,  cudaFuncAttributeMaxDynamicSharedMemorySize, SCAN_SMEM);
    cudaFuncSetAttribute(k_out,   cudaFuncAttributeMaxDynamicSharedMemorySize, OUT_SMEM);

    k_front<<<250, 256, FRONT_SMEM>>>(concept, correct, nc, ek, ev, Mk, We, be, Wa, ba);
    k_scan<<<256, 128, SCAN_SMEM>>>(Mv0);
    k_out<<<250, 256, OUT_SMEM>>>(concept, ek, Wf, bf, Wab, bab, Wd, bd, out);
}